// round 13
// baseline (speedup 1.0000x reference)
#include <cuda_runtime.h>

#define N_CELLS   776
#define N_ANCHORS 3
#define N_CH      7
#define N_THREADS 1024
#define CONF_THRESH 0.8f
#define NO_OBJECT   0.5f

__global__ void __launch_bounds__(N_THREADS, 1)
yolo_loss_kernel(const float* __restrict__ pred,
                 const float* __restrict__ label,
                 float* __restrict__ out)
{
    __shared__ float warp_sums[32];

    const int cell = threadIdx.x;
    float loss = 0.0f;

    // Label first: all 28 LDGs (7 broadcast + 21 per-cell) issue in one
    // front batch -> single latency exposure, then register-only compute.
    const float l0 = label[0], l1 = label[1], l2 = label[2], l3 = label[3];
    const float l4 = label[4], l5 = label[5], l6 = label[6];

    if (cell < N_CELLS) {
        const float* base = pred + cell * (N_ANCHORS * N_CH);

        float ch[N_ANCHORS][N_CH];
        #pragma unroll
        for (int a = 0; a < N_ANCHORS; a++)
            #pragma unroll
            for (int c = 0; c < N_CH; c++)
                ch[a][c] = base[a * N_CH + c];

        const float lx0 = l0 - l2 * 0.5f;
        const float ly0 = l1 - l3 * 0.5f;
        const float lx1 = l0 + l2 * 0.5f;
        const float ly1 = l1 + l3 * 0.5f;
        const float area_b = fabsf(l2 * l3);

        // IoU numerators/denominators; the quotient only feeds argmax.
        // den > 0 always (inter <= min(area_a, area_b)).
        float num[N_ANCHORS], den[N_ANCHORS];
        #pragma unroll
        for (int a = 0; a < N_ANCHORS; a++) {
            const float px = ch[a][0];
            const float py = ch[a][1];
            const float pw = ch[a][2];
            const float ph = ch[a][3];

            const float ax = fmaxf(px - pw * 0.5f, lx0);
            const float ay = fmaxf(py - ph * 0.5f, ly0);
            const float bx = fminf(px + pw * 0.5f, lx1);
            const float by = fminf(py + ph * 0.5f, ly1);

            const float inter = fabsf(fmaxf(bx - ax, 0.0f) * fmaxf(by - ay, 0.0f));
            const float area_a = fabsf(pw * ph);
            num[a] = inter;
            den[a] = area_a + area_b - inter;
        }

        // Division-free argmax, first-max tie-break (strict >):
        //   num[j]/den[j] > num[i]/den[i]  <=>  num[j]*den[i] > num[i]*den[j]
        float b0 = ch[0][0], b1 = ch[0][1], b4 = ch[0][4], b5 = ch[0][5], b6 = ch[0][6];
        float bn = num[0], bd = den[0];
        if (num[1] * bd > bn * den[1]) {
            bn = num[1]; bd = den[1];
            b0 = ch[1][0]; b1 = ch[1][1]; b4 = ch[1][4]; b5 = ch[1][5]; b6 = ch[1][6];
        }
        if (num[2] * bd > bn * den[2]) {   // bn/bd dead after this: no update
            b0 = ch[2][0]; b1 = ch[2][1]; b4 = ch[2][4]; b5 = ch[2][5]; b6 = ch[2][6];
        }

        // NOTE: wh_loss intentionally reuses indices 0/1 (x/y), replicating
        // the reference bit-exactly.
        const float dx = l0 - b0;
        const float dy = l1 - b1;
        const float xy_loss = dx * dx + dy * dy;

        const float sx = sqrtf(l0) - sqrtf(b0);
        const float sy = sqrtf(l1) - sqrtf(b1);
        const float wh_loss = sx * sx + sy * sy;

        const float coord_loss = xy_loss + wh_loss;

        const bool has_obj = b4 > CONF_THRESH;

        const float d5 = l5 - b5;
        const float d6 = l6 - b6;
        const float class_loss = has_obj ? (d5 * d5 + d6 * d6) : 0.0f;

        const float dc = l4 - b4;
        const float conf_sq = dc * dc;
        const float conf_loss = has_obj ? conf_sq : NO_OBJECT * conf_sq;

        loss = coord_loss + class_loss + conf_loss;
    }

    // ---- block reduction: warp shuffle, then 32 partials via warp 0 ----
    #pragma unroll
    for (int off = 16; off > 0; off >>= 1)
        loss += __shfl_down_sync(0xFFFFFFFFu, loss, off);

    const int lane = threadIdx.x & 31;
    const int warp = threadIdx.x >> 5;
    if (lane == 0) warp_sums[warp] = loss;
    __syncthreads();

    if (warp == 0) {
        float v = warp_sums[lane];   // exactly 32 warps at blockDim=1024
        #pragma unroll
        for (int off = 16; off > 0; off >>= 1)
            v += __shfl_down_sync(0xFFFFFFFFu, v, off);
        if (lane == 0) out[0] = v;
    }
}

extern "C" void kernel_launch(void* const* d_in, const int* in_sizes, int n_in,
                              void* d_out, int out_size)
{
    const float* pred  = (const float*)d_in[0];
    const float* label = (const float*)d_in[1];
    float* out = (float*)d_out;
    yolo_loss_kernel<<<1, N_THREADS>>>(pred, label, out);
}

// round 15
// speedup vs baseline: 1.1574x; 1.1574x over previous
#include <cuda_runtime.h>

#define N_CELLS   776
#define N_ANCHORS 3
#define N_CH      7
#define N_THREADS 1024
#define CONF_THRESH 0.8f
#define NO_OBJECT   0.5f

__global__ void __launch_bounds__(N_THREADS, 1)
yolo_loss_kernel(const float* __restrict__ pred,
                 const float* __restrict__ label,
                 float* __restrict__ out)
{
    __shared__ float warp_sums[32];

    const int cell = threadIdx.x;
    float loss = 0.0f;

    // Label first: all 28 LDGs (7 broadcast + 21 per-cell) issue in one
    // front batch -> single latency exposure, then register-only compute.
    const float l0 = label[0], l1 = label[1], l2 = label[2], l3 = label[3];
    const float l4 = label[4], l5 = label[5], l6 = label[6];

    if (cell < N_CELLS) {
        const float* base = pred + cell * (N_ANCHORS * N_CH);

        float ch[N_ANCHORS][N_CH];
        #pragma unroll
        for (int a = 0; a < N_ANCHORS; a++)
            #pragma unroll
            for (int c = 0; c < N_CH; c++)
                ch[a][c] = base[a * N_CH + c];

        const float lx0 = l0 - l2 * 0.5f;
        const float ly0 = l1 - l3 * 0.5f;
        const float lx1 = l0 + l2 * 0.5f;
        const float ly1 = l1 + l3 * 0.5f;
        const float area_b = fabsf(l2 * l3);

        // IoU numerators/denominators; the quotient only feeds argmax.
        // den > 0 always (inter <= min(area_a, area_b)).
        float num[N_ANCHORS], den[N_ANCHORS];
        #pragma unroll
        for (int a = 0; a < N_ANCHORS; a++) {
            const float px = ch[a][0];
            const float py = ch[a][1];
            const float pw = ch[a][2];
            const float ph = ch[a][3];

            const float ax = fmaxf(px - pw * 0.5f, lx0);
            const float ay = fmaxf(py - ph * 0.5f, ly0);
            const float bx = fminf(px + pw * 0.5f, lx1);
            const float by = fminf(py + ph * 0.5f, ly1);

            const float inter = fabsf(fmaxf(bx - ax, 0.0f) * fmaxf(by - ay, 0.0f));
            const float area_a = fabsf(pw * ph);
            num[a] = inter;
            den[a] = area_a + area_b - inter;
        }

        // Division-free argmax, first-max tie-break (strict >):
        //   num[j]/den[j] > num[i]/den[i]  <=>  num[j]*den[i] > num[i]*den[j]
        float b0 = ch[0][0], b1 = ch[0][1], b4 = ch[0][4], b5 = ch[0][5], b6 = ch[0][6];
        float bn = num[0], bd = den[0];
        if (num[1] * bd > bn * den[1]) {
            bn = num[1]; bd = den[1];
            b0 = ch[1][0]; b1 = ch[1][1]; b4 = ch[1][4]; b5 = ch[1][5]; b6 = ch[1][6];
        }
        if (num[2] * bd > bn * den[2]) {   // bn/bd dead after this: no update
            b0 = ch[2][0]; b1 = ch[2][1]; b4 = ch[2][4]; b5 = ch[2][5]; b6 = ch[2][6];
        }

        // NOTE: wh_loss intentionally reuses indices 0/1 (x/y), replicating
        // the reference bit-exactly.
        const float dx = l0 - b0;
        const float dy = l1 - b1;
        const float xy_loss = dx * dx + dy * dy;

        const float sx = sqrtf(l0) - sqrtf(b0);
        const float sy = sqrtf(l1) - sqrtf(b1);
        const float wh_loss = sx * sx + sy * sy;

        const float coord_loss = xy_loss + wh_loss;

        const bool has_obj = b4 > CONF_THRESH;

        const float d5 = l5 - b5;
        const float d6 = l6 - b6;
        const float class_loss = has_obj ? (d5 * d5 + d6 * d6) : 0.0f;

        const float dc = l4 - b4;
        const float conf_sq = dc * dc;
        const float conf_loss = has_obj ? conf_sq : NO_OBJECT * conf_sq;

        loss = coord_loss + class_loss + conf_loss;
    }

    // ---- block reduction: warp shuffle, then 32 partials via warp 0 ----
    #pragma unroll
    for (int off = 16; off > 0; off >>= 1)
        loss += __shfl_down_sync(0xFFFFFFFFu, loss, off);

    const int lane = threadIdx.x & 31;
    const int warp = threadIdx.x >> 5;
    if (lane == 0) warp_sums[warp] = loss;
    __syncthreads();

    if (warp == 0) {
        float v = warp_sums[lane];   // exactly 32 warps at blockDim=1024
        #pragma unroll
        for (int off = 16; off > 0; off >>= 1)
            v += __shfl_down_sync(0xFFFFFFFFu, v, off);
        if (lane == 0) out[0] = v;
    }
}

extern "C" void kernel_launch(void* const* d_in, const int* in_sizes, int n_in,
                              void* d_out, int out_size)
{
    const float* pred  = (const float*)d_in[0];
    const float* label = (const float*)d_in[1];
    float* out = (float*)d_out;
    yolo_loss_kernel<<<1, N_THREADS>>>(pred, label, out);
}

// round 16
// speedup vs baseline: 1.2077x; 1.0435x over previous
#include <cuda_runtime.h>

#define N_CELLS   776
#define N_ANCHORS 3
#define N_CH      7
#define N_THREADS 1024
#define CONF_THRESH 0.8f
#define NO_OBJECT   0.5f

__global__ void __launch_bounds__(N_THREADS, 1)
yolo_loss_kernel(const float* __restrict__ pred,
                 const float* __restrict__ label,
                 float* __restrict__ out)
{
    __shared__ float warp_sums[32];

    const int cell = threadIdx.x;
    float loss = 0.0f;

    // Vectorized label load: harness buffers are >=256B aligned, so
    // float4 + float2 + float is legal -> 3 LDGs instead of 7, all broadcast.
    const float4 lv0 = *reinterpret_cast<const float4*>(label);
    const float2 lv1 = *reinterpret_cast<const float2*>(label + 4);
    const float  l6  = label[6];
    const float l0 = lv0.x, l1 = lv0.y, l2 = lv0.z, l3 = lv0.w;
    const float l4 = lv1.x, l5 = lv1.y;

    if (cell < N_CELLS) {
        const float* base = pred + cell * (N_ANCHORS * N_CH);

        // Front-batched per-cell loads: 21 scalar LDGs, one latency exposure.
        float ch[N_ANCHORS][N_CH];
        #pragma unroll
        for (int a = 0; a < N_ANCHORS; a++)
            #pragma unroll
            for (int c = 0; c < N_CH; c++)
                ch[a][c] = base[a * N_CH + c];

        const float lx0 = l0 - l2 * 0.5f;
        const float ly0 = l1 - l3 * 0.5f;
        const float lx1 = l0 + l2 * 0.5f;
        const float ly1 = l1 + l3 * 0.5f;
        const float area_b = fabsf(l2 * l3);

        // IoU numerators/denominators; the quotient only feeds argmax.
        // den > 0 always (inter <= min(area_a, area_b)).
        float num[N_ANCHORS], den[N_ANCHORS];
        #pragma unroll
        for (int a = 0; a < N_ANCHORS; a++) {
            const float px = ch[a][0];
            const float py = ch[a][1];
            const float pw = ch[a][2];
            const float ph = ch[a][3];

            const float ax = fmaxf(px - pw * 0.5f, lx0);
            const float ay = fmaxf(py - ph * 0.5f, ly0);
            const float bx = fminf(px + pw * 0.5f, lx1);
            const float by = fminf(py + ph * 0.5f, ly1);

            const float inter = fabsf(fmaxf(bx - ax, 0.0f) * fmaxf(by - ay, 0.0f));
            const float area_a = fabsf(pw * ph);
            num[a] = inter;
            den[a] = area_a + area_b - inter;
        }

        // Division-free argmax, first-max tie-break (strict >):
        //   num[j]/den[j] > num[i]/den[i]  <=>  num[j]*den[i] > num[i]*den[j]
        float b0 = ch[0][0], b1 = ch[0][1], b4 = ch[0][4], b5 = ch[0][5], b6 = ch[0][6];
        float bn = num[0], bd = den[0];
        if (num[1] * bd > bn * den[1]) {
            bn = num[1]; bd = den[1];
            b0 = ch[1][0]; b1 = ch[1][1]; b4 = ch[1][4]; b5 = ch[1][5]; b6 = ch[1][6];
        }
        if (num[2] * bd > bn * den[2]) {   // bn/bd dead after this: no update
            b0 = ch[2][0]; b1 = ch[2][1]; b4 = ch[2][4]; b5 = ch[2][5]; b6 = ch[2][6];
        }

        // NOTE: wh_loss intentionally reuses indices 0/1 (x/y), replicating
        // the reference bit-exactly.
        const float dx = l0 - b0;
        const float dy = l1 - b1;
        const float xy_loss = dx * dx + dy * dy;

        const float sx = sqrtf(l0) - sqrtf(b0);
        const float sy = sqrtf(l1) - sqrtf(b1);
        const float wh_loss = sx * sx + sy * sy;

        const float coord_loss = xy_loss + wh_loss;

        const bool has_obj = b4 > CONF_THRESH;

        const float d5 = l5 - b5;
        const float d6 = l6 - b6;
        const float class_loss = has_obj ? (d5 * d5 + d6 * d6) : 0.0f;

        const float dc = l4 - b4;
        const float conf_sq = dc * dc;
        const float conf_loss = has_obj ? conf_sq : NO_OBJECT * conf_sq;

        loss = coord_loss + class_loss + conf_loss;
    }

    // ---- block reduction: warp shuffle, then 32 partials via warp 0 ----
    #pragma unroll
    for (int off = 16; off > 0; off >>= 1)
        loss += __shfl_down_sync(0xFFFFFFFFu, loss, off);

    const int lane = threadIdx.x & 31;
    const int warp = threadIdx.x >> 5;
    if (lane == 0) warp_sums[warp] = loss;
    __syncthreads();

    if (warp == 0) {
        float v = warp_sums[lane];   // exactly 32 warps at blockDim=1024
        #pragma unroll
        for (int off = 16; off > 0; off >>= 1)
            v += __shfl_down_sync(0xFFFFFFFFu, v, off);
        if (lane == 0) out[0] = v;
    }
}

extern "C" void kernel_launch(void* const* d_in, const int* in_sizes, int n_in,
                              void* d_out, int out_size)
{
    const float* pred  = (const float*)d_in[0];
    const float* label = (const float*)d_in[1];
    float* out = (float*)d_out;
    yolo_loss_kernel<<<1, N_THREADS>>>(pred, label, out);
}